// round 9
// baseline (speedup 1.0000x reference)
#include <cuda_runtime.h>
#include <cuda_bf16.h>
#include <math.h>
#include <stdint.h>

#define NN 50000
#define DD 128
#define EE 500000
#define NWT (EE / 16)      // 31250 warp-tiles per side, exact
#define TOTWT (2 * NWT)    // both sides

// ---------------- device scratch ----------------
// pack rows: 32 groups of 16B = [x16 4cols (8B) | A1-or-C1 4cols (8B)]
static __device__ __nv_bfloat16 g_pA_a[NN*256];   // x_a | lrelu(xa@Wp.T+bp)@W1p.T + b1
static __device__ __nv_bfloat16 g_pC_a[NN*256];   // x_a | lrelu(xa@Wc.T+bc)@W1c.T
static __device__ __nv_bfloat16 g_pA_b[NN*256];
static __device__ __nv_bfloat16 g_pC_b[NN*256];
static __device__ float g_msg_a[NN*DD];
static __device__ float g_msg_b[NN*DD];

__device__ __forceinline__ uint32_t smem_u32(const void* p) {
    uint32_t a;
    asm("{ .reg .u64 t; cvta.to.shared.u64 t, %1; cvt.u32.u64 %0, t; }" : "=r"(a) : "l"(p));
    return a;
}
__device__ __forceinline__ void ldsm_x4(uint32_t* r, uint32_t addr) {
    asm volatile("ldmatrix.sync.aligned.m8n8.x4.shared.b16 {%0,%1,%2,%3}, [%4];"
                 : "=r"(r[0]), "=r"(r[1]), "=r"(r[2]), "=r"(r[3]) : "r"(addr));
}
__device__ __forceinline__ void mma_bf16(float* c, const uint32_t* a, const uint32_t* b) {
    asm volatile("mma.sync.aligned.m16n8k16.row.col.f32.bf16.bf16.f32 "
                 "{%0,%1,%2,%3}, {%4,%5,%6,%7}, {%8,%9}, {%0,%1,%2,%3};"
                 : "+f"(c[0]), "+f"(c[1]), "+f"(c[2]), "+f"(c[3])
                 : "r"(a[0]), "r"(a[1]), "r"(a[2]), "r"(a[3]), "r"(b[0]), "r"(b[1]));
}
__device__ __forceinline__ void red_add_v4(float* p, float a, float b, float c, float d) {
    asm volatile("red.global.add.v4.f32 [%0], {%1, %2, %3, %4};"
                 :: "l"(p), "f"(a), "f"(b), "f"(c), "f"(d) : "memory");
}
__device__ __forceinline__ __nv_bfloat162 u2bf2(uint32_t u) {
    return *reinterpret_cast<__nv_bfloat162*>(&u);
}
__device__ __forceinline__ uint32_t bf2u(__nv_bfloat162 h) {
    return *reinterpret_cast<uint32_t*>(&h);
}

// 16-row x 128-col x K=128 warp MMA, stride-272 bf16 smem tiles; paired-B ldsm_x4.
// b4_base must include: (lane&7)*272 + ((lane>>3)&1)*16 + (lane>>4)*2176
__device__ __forceinline__ void mma_rows16(uint32_t a_addr0, uint32_t b4_base, float acc[16][4]) {
    #pragma unroll
    for (int k = 0; k < 8; k++) {
        uint32_t afrag[4];
        ldsm_x4(afrag, a_addr0 + k * 32);
        uint32_t bb = b4_base + k * 32;
        #pragma unroll
        for (int ntp = 0; ntp < 8; ntp++) {
            uint32_t bfrag[4];
            ldsm_x4(bfrag, bb + ntp * 4352);
            mma_bf16(acc[2*ntp],     afrag, bfrag);
            mma_bf16(acc[2*ntp + 1], afrag, bfrag + 2);
        }
    }
}

// ---------------- zero msg ----------------
__global__ void zero_kernel() {
    int i = blockIdx.x * blockDim.x + threadIdx.x;
    float4 z = make_float4(0.f, 0.f, 0.f, 0.f);
    if (i < NN * DD / 4) {
        reinterpret_cast<float4*>(g_msg_a)[i] = z;
        reinterpret_cast<float4*>(g_msg_b)[i] = z;
    }
}

// ---------------- node precompute: merged chains, packed output ----------------
#define NP_WT   0         // bf16 [128][272] -> 34816
#define NP_UT   34816     // bf16 [128][272] -> 69632
#define NP_XS   69632     // bf16 [256][272] -> 139264
#define NP_TS   139264    // bf16 [256][272] -> 208896
#define NP_BENC 208896    // 2 x 128 floats (bp, bc)
#define NP_B1   209920    // 128 floats
#define NP_TOTAL 210432

__global__ __launch_bounds__(512, 1) void node_pre_kernel(
    const float* __restrict__ x_a, const float* __restrict__ x_b,
    const float* __restrict__ Wp, const float* __restrict__ bp,
    const float* __restrict__ Wc, const float* __restrict__ bc,
    const float* __restrict__ W1, const float* __restrict__ b1)
{
    extern __shared__ char smc[];
    uint32_t smb = smem_u32(smc);
    float* benc = (float*)(smc + NP_BENC);
    float* b1sm = (float*)(smc + NP_B1);

    int sidex = blockIdx.y;
    const float* X = sidex ? x_b : x_a;
    __nv_bfloat16* PackA = sidex ? g_pA_b : g_pA_a;
    __nv_bfloat16* PackC = sidex ? g_pC_b : g_pC_a;

    int tid = threadIdx.x, lane = tid & 31, w = tid >> 5;
    int nbase = blockIdx.x * 256;

    for (int idx = tid; idx < 256 * 32; idx += 512) {
        int row = idx >> 5, cp = idx & 31;
        int n = nbase + row;
        float4 f = make_float4(0.f, 0.f, 0.f, 0.f);
        if (n < NN) f = *reinterpret_cast<const float4*>(X + (size_t)n * 128 + cp * 4);
        uint2 pk;
        pk.x = bf2u(__floats2bfloat162_rn(f.x, f.y));
        pk.y = bf2u(__floats2bfloat162_rn(f.z, f.w));
        *reinterpret_cast<uint2*>(smc + NP_XS + row * 272 + cp * 8) = pk;
    }
    if (tid < 128) {
        benc[tid]       = bp[tid];
        benc[128 + tid] = bc[tid];
        b1sm[tid]       = b1[tid];
    }

    uint32_t a_lane_off  = (uint32_t)(lane & 15) * 272 + (((uint32_t)lane >> 4) << 4);
    uint32_t b4_lane_off = (uint32_t)(lane & 7) * 272 + ((((uint32_t)lane >> 3) & 1) << 4)
                         + (((uint32_t)lane >> 4) * 2176);
    int r0 = 16 * w + (lane >> 2), r1 = r0 + 8;
    int cq = (lane & 3) * 2;
    int n0 = nbase + r0, n1 = nbase + r1;

    for (int cc = 0; cc < 2; cc++) {
        const float* W = cc ? Wc : Wp;
        int off = cc ? 128 : 0;
        __nv_bfloat16* Pack = cc ? PackC : PackA;

        for (int idx = tid; idx < 128 * 64; idx += 512) {
            int i = idx >> 6, cp = idx & 63;
            float2 fw = *reinterpret_cast<const float2*>(W + i * 128 + cp * 2);
            float2 fu = *reinterpret_cast<const float2*>(W1 + i * 384 + off + cp * 2);
            *(uint32_t*)(smc + NP_WT + i * 272 + cp * 4) = bf2u(__floats2bfloat162_rn(fw.x, fw.y));
            *(uint32_t*)(smc + NP_UT + i * 272 + cp * 4) = bf2u(__floats2bfloat162_rn(fu.x, fu.y));
        }
        __syncthreads();

        float acc[16][4];
        #pragma unroll
        for (int nt = 0; nt < 16; nt++)
            #pragma unroll
            for (int q = 0; q < 4; q++) acc[nt][q] = 0.f;
        mma_rows16(smb + NP_XS + (uint32_t)(16 * w) * 272 + a_lane_off, smb + NP_WT + b4_lane_off, acc);

        #pragma unroll
        for (int nt = 0; nt < 16; nt++) {
            int c = nt * 8 + cq;
            float2 bb = *reinterpret_cast<const float2*>(benc + cc * 128 + c);
            float v0 = acc[nt][0] + bb.x, v1 = acc[nt][1] + bb.y;
            float v2 = acc[nt][2] + bb.x, v3 = acc[nt][3] + bb.y;
            v0 = v0 > 0.f ? v0 : 0.01f * v0;
            v1 = v1 > 0.f ? v1 : 0.01f * v1;
            v2 = v2 > 0.f ? v2 : 0.01f * v2;
            v3 = v3 > 0.f ? v3 : 0.01f * v3;
            *(uint32_t*)(smc + NP_TS + r0 * 272 + c * 2) = bf2u(__floats2bfloat162_rn(v0, v1));
            *(uint32_t*)(smc + NP_TS + r1 * 272 + c * 2) = bf2u(__floats2bfloat162_rn(v2, v3));
        }
        __syncwarp();

        #pragma unroll
        for (int nt = 0; nt < 16; nt++)
            #pragma unroll
            for (int q = 0; q < 4; q++) acc[nt][q] = 0.f;
        mma_rows16(smb + NP_TS + (uint32_t)(16 * w) * 272 + a_lane_off, smb + NP_UT + b4_lane_off, acc);

        // packed store: [x pair | A1/C1 pair] per 16B group
        #pragma unroll
        for (int nt = 0; nt < 16; nt++) {
            int c = nt * 8 + cq;
            float bx = (cc == 0) ? b1sm[c] : 0.f;
            float by = (cc == 0) ? b1sm[c + 1] : 0.f;
            uint32_t h0 = bf2u(__floats2bfloat162_rn(acc[nt][0] + bx, acc[nt][1] + by));
            uint32_t h1 = bf2u(__floats2bfloat162_rn(acc[nt][2] + bx, acc[nt][3] + by));
            uint32_t x0 = *(const uint32_t*)(smc + NP_XS + r0 * 272 + c * 2);
            uint32_t x1 = *(const uint32_t*)(smc + NP_XS + r1 * 272 + c * 2);
            uint32_t goff = ((uint32_t)(c >> 2) << 4) + (((uint32_t)c & 3) << 1);
            if (n0 < NN) {
                char* base = (char*)Pack + (size_t)n0 * 512 + goff;
                *(uint32_t*)(base) = x0;
                *(uint32_t*)(base + 8) = h0;
            }
            if (n1 < NN) {
                char* base = (char*)Pack + (size_t)n1 * 512 + goff;
                *(uint32_t*)(base) = x1;
                *(uint32_t*)(base + 8) = h1;
            }
        }
        __syncthreads();
    }
}

// ---------------- edge kernel: merged sides, packed gather, paired-B mma ----------------
#define EP_W2   0          // 128 floats -> 512
#define EP_W1D  512        // bf16 [128][272] -> 35328
#define EP_DIFF 35328      // bf16 [128][272] -> 70144
#define EP_PRES 70144      // bf16 [128][272] -> 104960
#define EP_TOTAL 104960

__global__ __launch_bounds__(256, 2) void edge_mma_kernel(
    const float* __restrict__ x_a, const float* __restrict__ x_b,
    const int* __restrict__ ei_ab, const int* __restrict__ ei_ba,
    const float* __restrict__ W1,
    const float* __restrict__ W2, const float* __restrict__ b2)
{
    extern __shared__ char smc[];
    uint32_t smb = smem_u32(smc);
    float* w2s = (float*)(smc + EP_W2);

    int tid = threadIdx.x, lane = tid & 31, w = tid >> 5;

    for (int idx = tid; idx < 128 * 64; idx += 256) {
        int i = idx >> 6, cp = idx & 63;
        float2 f = *reinterpret_cast<const float2*>(W1 + i * 384 + 256 + cp * 2);
        *(uint32_t*)(smc + EP_W1D + i * 272 + cp * 4) = bf2u(__floats2bfloat162_rn(f.x, f.y));
    }
    if (tid < 128) w2s[tid] = W2[tid];
    float b2s = __ldg(b2);
    __syncthreads();

    uint32_t a_addr0 = smb + EP_DIFF + (uint32_t)(16 * w + (lane & 15)) * 272 + (((uint32_t)lane >> 4) << 4);
    uint32_t b4_base = smb + EP_W1D + (uint32_t)(lane & 7) * 272 + ((((uint32_t)lane >> 3) & 1) << 4)
                     + (((uint32_t)lane >> 4) * 2176);
    int r0 = 16 * w + (lane >> 2), r1 = r0 + 8;
    int cq = (lane & 3) * 2;
    int li16 = lane & 15;
    int isdst = lane >> 4;   // lanes 16-31 load dst ids

    const int wstride = gridDim.x * 8;
    int wt = blockIdx.x * 8 + w;
    if (wt >= TOTWT) return;

    // initial index load for first tile
    int side = wt & 1;
    const int* ei = side ? ei_ba : ei_ab;
    int vidx = __ldg(ei + isdst * EE + (wt >> 1) * 16 + li16);

    while (true) {
        int ebase16 = (wt >> 1) * 16;   // silence: ebase implicit in vidx
        (void)ebase16;
        const float* srcf = side ? x_b : x_a;
        const __nv_bfloat16* pS = side ? g_pA_b : g_pA_a;   // src pack: x | A1
        const __nv_bfloat16* pD = side ? g_pC_a : g_pC_b;   // dst pack: x | C1
        float* msg = side ? g_msg_a : g_msg_b;

        // ---- gather: 2 packed 16B loads per edge per lane ----
        #pragma unroll
        for (int i = 0; i < 16; i++) {
            int s = __shfl_sync(0xffffffffu, vidx, i);
            int t = __shfl_sync(0xffffffffu, vidx, 16 + i);
            int le = 16 * w + i;
            uint4 pa = *reinterpret_cast<const uint4*>(pS + (size_t)s * 256 + lane * 8);
            uint4 pc = *reinterpret_cast<const uint4*>(pD + (size_t)t * 256 + lane * 8);
            uint2 dpk, ppk;
            dpk.x = bf2u(__habs2(__hsub2(u2bf2(pa.x), u2bf2(pc.x))));
            dpk.y = bf2u(__habs2(__hsub2(u2bf2(pa.y), u2bf2(pc.y))));
            ppk.x = bf2u(__hadd2(u2bf2(pa.z), u2bf2(pc.z)));
            ppk.y = bf2u(__hadd2(u2bf2(pa.w), u2bf2(pc.w)));
            *reinterpret_cast<uint2*>(smc + EP_DIFF + le * 272 + lane * 8) = dpk;
            *reinterpret_cast<uint2*>(smc + EP_PRES + le * 272 + lane * 8) = ppk;
        }
        __syncwarp();

        // ---- prefetch next tile's indices (latency hidden under mma) ----
        int wtn = wt + wstride;
        int vnext = 0;
        int nside = wtn & 1;
        if (wtn < TOTWT) {
            const int* ein = nside ? ei_ba : ei_ab;
            vnext = __ldg(ein + isdst * EE + (wtn >> 1) * 16 + li16);
        }

        // ---- mma ----
        float acc[16][4];
        #pragma unroll
        for (int nt = 0; nt < 16; nt++)
            #pragma unroll
            for (int q = 0; q < 4; q++) acc[nt][q] = 0.f;
        mma_rows16(a_addr0, b4_base, acc);

        // ---- fused epilogue ----
        float z0 = 0.f, z1 = 0.f;
        #pragma unroll
        for (int nt = 0; nt < 16; nt++) {
            int c = nt * 8 + cq;
            float2 p0 = __bfloat1622float2(*reinterpret_cast<const __nv_bfloat162*>(smc + EP_PRES + r0 * 272 + c * 2));
            float2 p1 = __bfloat1622float2(*reinterpret_cast<const __nv_bfloat162*>(smc + EP_PRES + r1 * 272 + c * 2));
            float2 w2v = *reinterpret_cast<const float2*>(w2s + c);
            z0 += fmaxf(p0.x + acc[nt][0], 0.f) * w2v.x + fmaxf(p0.y + acc[nt][1], 0.f) * w2v.y;
            z1 += fmaxf(p1.x + acc[nt][2], 0.f) * w2v.x + fmaxf(p1.y + acc[nt][3], 0.f) * w2v.y;
        }
        z0 += __shfl_xor_sync(0xffffffffu, z0, 1);
        z0 += __shfl_xor_sync(0xffffffffu, z0, 2);
        z1 += __shfl_xor_sync(0xffffffffu, z1, 1);
        z1 += __shfl_xor_sync(0xffffffffu, z1, 2);
        float sig0 = 1.f / (1.f + expf(-(z0 + b2s)));
        float sig1 = 1.f / (1.f + expf(-(z1 + b2s)));
        __syncwarp();   // PRES reads done before next-tile gather overwrites

        // ---- scatter: weights + indices via shfl, fp32 src rows, v4 red ----
        #pragma unroll
        for (int i = 0; i < 16; i++) {
            int s = __shfl_sync(0xffffffffu, vidx, i);
            int t = __shfl_sync(0xffffffffu, vidx, 16 + i);
            float wg = __shfl_sync(0xffffffffu, (i < 8) ? sig0 : sig1, (i & 7) * 4);
            float4 p = *reinterpret_cast<const float4*>(srcf + (size_t)s * 128 + 4 * lane);
            float* mr = msg + (size_t)t * 128 + 4 * lane;
            red_add_v4(mr, wg * p.x, wg * p.y, wg * p.z, wg * p.w);
        }

        if (wtn >= TOTWT) break;
        wt = wtn;
        side = nside;
        vidx = vnext;
    }
}

// ---------------- final: bf16x3 split-precision mma ----------------
#define FI_BHI 0          // bf16 [128][272] -> 34816
#define FI_BLO 34816      // -> 69632
#define FI_AHI 69632      // bf16 [256][272] -> 139264
#define FI_ALO 139264     // -> 208896
#define FI_BS  208896     // 128 floats
#define FI_TOTAL 209408

__global__ __launch_bounds__(512, 1) void final_kernel(
    const float* __restrict__ x_a, const float* __restrict__ x_b,
    const float* __restrict__ Wrel_ab, const float* __restrict__ brel_ab,
    const float* __restrict__ Wroot_ab, const float* __restrict__ broot_ab,
    const float* __restrict__ Wrel_ba, const float* __restrict__ brel_ba,
    const float* __restrict__ Wroot_ba, const float* __restrict__ broot_ba,
    float* __restrict__ out)
{
    extern __shared__ char smc[];
    uint32_t smb = smem_u32(smc);
    float* bsf = (float*)(smc + FI_BS);

    int side = blockIdx.y;
    const float* x     = side ? x_b : x_a;
    const float* msg   = side ? g_msg_b : g_msg_a;
    const float* Wrel  = side ? Wrel_ab  : Wrel_ba;
    const float* brel  = side ? brel_ab  : brel_ba;
    const float* Wroot = side ? Wroot_ab : Wroot_ba;
    const float* broot = side ? broot_ab : broot_ba;
    float* o = out + (size_t)side * NN * DD;

    int tid = threadIdx.x, lane = tid & 31, w = tid >> 5;
    int nbase = blockIdx.x * 256;

    if (tid < 128) bsf[tid] = brel[tid] + broot[tid];

    uint32_t a_lane_off  = (uint32_t)(lane & 15) * 272 + (((uint32_t)lane >> 4) << 4);
    uint32_t b4_lane_off = (uint32_t)(lane & 7) * 272 + ((((uint32_t)lane >> 3) & 1) << 4)
                         + (((uint32_t)lane >> 4) * 2176);
    uint32_t a_base = smb + FI_AHI + (uint32_t)(16 * w) * 272 + a_lane_off;
    uint32_t a_base_lo = a_base + (FI_ALO - FI_AHI);

    float acc[16][4];
    #pragma unroll
    for (int nt = 0; nt < 16; nt++)
        #pragma unroll
        for (int q = 0; q < 4; q++) acc[nt][q] = 0.f;

    for (int term = 0; term < 2; term++) {
        const float* Asrc = term ? x : msg;
        const float* Bsrc = term ? Wroot : Wrel;
        if (term) __syncthreads();

        for (int idx = tid; idx < 128 * 64; idx += 512) {
            int i = idx >> 6, cp = idx & 63;
            float2 v = *reinterpret_cast<const float2*>(Bsrc + i * 128 + cp * 2);
            __nv_bfloat162 h = __floats2bfloat162_rn(v.x, v.y);
            float2 hf = __bfloat1622float2(h);
            __nv_bfloat162 l = __floats2bfloat162_rn(v.x - hf.x, v.y - hf.y);
            *(uint32_t*)(smc + FI_BHI + i * 272 + cp * 4) = bf2u(h);
            *(uint32_t*)(smc + FI_BLO + i * 272 + cp * 4) = bf2u(l);
        }
        for (int idx = tid; idx < 256 * 32; idx += 512) {
            int row = idx >> 5, cp = idx & 31;
            int n = nbase + row;
            float4 v = make_float4(0.f, 0.f, 0.f, 0.f);
            if (n < NN) v = *reinterpret_cast<const float4*>(Asrc + (size_t)n * 128 + cp * 4);
            __nv_bfloat162 h0 = __floats2bfloat162_rn(v.x, v.y);
            __nv_bfloat162 h1 = __floats2bfloat162_rn(v.z, v.w);
            float2 f0 = __bfloat1622float2(h0);
            float2 f1 = __bfloat1622float2(h1);
            uint2 ph, pl;
            ph.x = bf2u(h0);
            ph.y = bf2u(h1);
            pl.x = bf2u(__floats2bfloat162_rn(v.x - f0.x, v.y - f0.y));
            pl.y = bf2u(__floats2bfloat162_rn(v.z - f1.x, v.w - f1.y));
            *reinterpret_cast<uint2*>(smc + FI_AHI + row * 272 + cp * 8) = ph;
            *reinterpret_cast<uint2*>(smc + FI_ALO + row * 272 + cp * 8) = pl;
        }
        __syncthreads();

        mma_rows16(a_base,    smb + FI_BHI + b4_lane_off, acc);
        mma_rows16(a_base,    smb + FI_BLO + b4_lane_off, acc);
        mma_rows16(a_base_lo, smb + FI_BHI + b4_lane_off, acc);
    }

    int r0 = 16 * w + (lane >> 2), r1 = r0 + 8;
    int cq = (lane & 3) * 2;
    int n0 = nbase + r0, n1 = nbase + r1;
    #pragma unroll
    for (int nt = 0; nt < 16; nt++) {
        int c = nt * 8 + cq;
        float2 bb = *reinterpret_cast<const float2*>(bsf + c);
        if (n0 < NN) {
            float2 v = make_float2(acc[nt][0] + bb.x, acc[nt][1] + bb.y);
            *reinterpret_cast<float2*>(o + (size_t)n0 * 128 + c) = v;
        }
        if (n1 < NN) {
            float2 v = make_float2(acc[nt][2] + bb.x, acc[nt][3] + bb.y);
            *reinterpret_cast<float2*>(o + (size_t)n1 * 128 + c) = v;
        }
    }
}

// ---------------- host ----------------
extern "C" void kernel_launch(void* const* d_in, const int* in_sizes, int n_in,
                              void* d_out, int out_size)
{
    const float* x_a = (const float*)d_in[0];
    const float* x_b = (const float*)d_in[1];
    const float* Wp  = (const float*)d_in[2];
    const float* bp  = (const float*)d_in[3];
    const float* Wc  = (const float*)d_in[4];
    const float* bc  = (const float*)d_in[5];
    const float* W1  = (const float*)d_in[6];
    const float* b1  = (const float*)d_in[7];
    const float* W2  = (const float*)d_in[8];
    const float* b2  = (const float*)d_in[9];
    const float* Wrel_ab  = (const float*)d_in[10];
    const float* brel_ab  = (const float*)d_in[11];
    const float* Wroot_ab = (const float*)d_in[12];
    const float* broot_ab = (const float*)d_in[13];
    const float* Wrel_ba  = (const float*)d_in[14];
    const float* brel_ba  = (const float*)d_in[15];
    const float* Wroot_ba = (const float*)d_in[16];
    const float* broot_ba = (const float*)d_in[17];
    const int* ei_ab = (const int*)d_in[18];
    const int* ei_ba = (const int*)d_in[19];
    float* out = (float*)d_out;

    cudaFuncSetAttribute(node_pre_kernel, cudaFuncAttributeMaxDynamicSharedMemorySize, NP_TOTAL);
    cudaFuncSetAttribute(edge_mma_kernel, cudaFuncAttributeMaxDynamicSharedMemorySize, EP_TOTAL);
    cudaFuncSetAttribute(final_kernel,    cudaFuncAttributeMaxDynamicSharedMemorySize, FI_TOTAL);

    zero_kernel<<<(NN * DD / 4 + 255) / 256, 256>>>();
    node_pre_kernel<<<dim3((NN + 255) / 256, 2), 512, NP_TOTAL>>>(x_a, x_b, Wp, bp, Wc, bc, W1, b1);
    edge_mma_kernel<<<296, 256, EP_TOTAL>>>(x_a, x_b, ei_ab, ei_ba, W1, W2, b2);
    final_kernel<<<dim3((NN + 255) / 256, 2), 512, FI_TOTAL>>>(
        x_a, x_b, Wrel_ab, brel_ab, Wroot_ab, broot_ab,
        Wrel_ba, brel_ba, Wroot_ba, broot_ba, out);
}

// round 10
// speedup vs baseline: 1.0948x; 1.0948x over previous
#include <cuda_runtime.h>
#include <cuda_bf16.h>
#include <math.h>
#include <stdint.h>

#define NN 50000
#define DD 128
#define EE 500000
#define NWT (EE / 16)    // 31250 warp-tiles, exact

// ---------------- device scratch ----------------
static __device__ __nv_bfloat16 g_A1a[NN*DD];   // lrelu(x_a@Wp.T+bp)@W1p.T + b1
static __device__ __nv_bfloat16 g_C1a[NN*DD];   // lrelu(x_a@Wc.T+bc)@W1c.T
static __device__ __nv_bfloat16 g_A1b[NN*DD];
static __device__ __nv_bfloat16 g_C1b[NN*DD];
static __device__ __nv_bfloat16 g_xa16[NN*DD];  // bf16 copies of x (gather path)
static __device__ __nv_bfloat16 g_xb16[NN*DD];
static __device__ float g_msg_a[NN*DD];
static __device__ float g_msg_b[NN*DD];

__device__ __forceinline__ uint32_t smem_u32(const void* p) {
    uint32_t a;
    asm("{ .reg .u64 t; cvta.to.shared.u64 t, %1; cvt.u32.u64 %0, t; }" : "=r"(a) : "l"(p));
    return a;
}
__device__ __forceinline__ void ldsm_x4(uint32_t* r, uint32_t addr) {
    asm volatile("ldmatrix.sync.aligned.m8n8.x4.shared.b16 {%0,%1,%2,%3}, [%4];"
                 : "=r"(r[0]), "=r"(r[1]), "=r"(r[2]), "=r"(r[3]) : "r"(addr));
}
__device__ __forceinline__ void ldsm_x2(uint32_t* r, uint32_t addr) {
    asm volatile("ldmatrix.sync.aligned.m8n8.x2.shared.b16 {%0,%1}, [%2];"
                 : "=r"(r[0]), "=r"(r[1]) : "r"(addr));
}
__device__ __forceinline__ void mma_bf16(float* c, const uint32_t* a, const uint32_t* b) {
    asm volatile("mma.sync.aligned.m16n8k16.row.col.f32.bf16.bf16.f32 "
                 "{%0,%1,%2,%3}, {%4,%5,%6,%7}, {%8,%9}, {%0,%1,%2,%3};"
                 : "+f"(c[0]), "+f"(c[1]), "+f"(c[2]), "+f"(c[3])
                 : "r"(a[0]), "r"(a[1]), "r"(a[2]), "r"(a[3]), "r"(b[0]), "r"(b[1]));
}
__device__ __forceinline__ void red_add_v4(float* p, float a, float b, float c, float d) {
    asm volatile("red.global.add.v4.f32 [%0], {%1, %2, %3, %4};"
                 :: "l"(p), "f"(a), "f"(b), "f"(c), "f"(d) : "memory");
}
__device__ __forceinline__ __nv_bfloat162 u2bf2(uint32_t u) {
    return *reinterpret_cast<__nv_bfloat162*>(&u);
}
__device__ __forceinline__ uint32_t bf2u(__nv_bfloat162 h) {
    return *reinterpret_cast<uint32_t*>(&h);
}

// 16-row x 128-col x K=128 warp MMA over stride-272 bf16 smem tiles; accumulates.
__device__ __forceinline__ void mma_rows16(uint32_t a_addr0, uint32_t b_base, float acc[16][4]) {
    #pragma unroll
    for (int k = 0; k < 8; k++) {
        uint32_t afrag[4];
        ldsm_x4(afrag, a_addr0 + k * 32);
        uint32_t bb = b_base + k * 32;
        #pragma unroll
        for (int nt = 0; nt < 16; nt++) {
            uint32_t bfrag[2];
            ldsm_x2(bfrag, bb + nt * 2176);
            mma_bf16(acc[nt], afrag, bfrag);
        }
    }
}

// ---------------- zero msg + make bf16 x copies ----------------
__global__ void zero_cvt_kernel(const float* __restrict__ xa, const float* __restrict__ xb) {
    int i = blockIdx.x * blockDim.x + threadIdx.x;
    if (i < NN * DD / 4) {
        float4 z = make_float4(0.f, 0.f, 0.f, 0.f);
        reinterpret_cast<float4*>(g_msg_a)[i] = z;
        reinterpret_cast<float4*>(g_msg_b)[i] = z;
        float4 a = reinterpret_cast<const float4*>(xa)[i];
        float4 b = reinterpret_cast<const float4*>(xb)[i];
        uint2 pa, pb;
        pa.x = bf2u(__floats2bfloat162_rn(a.x, a.y));
        pa.y = bf2u(__floats2bfloat162_rn(a.z, a.w));
        pb.x = bf2u(__floats2bfloat162_rn(b.x, b.y));
        pb.y = bf2u(__floats2bfloat162_rn(b.z, b.w));
        reinterpret_cast<uint2*>(g_xa16)[i] = pa;
        reinterpret_cast<uint2*>(g_xb16)[i] = pb;
    }
}

// ---------------- node precompute: merged chains per side ----------------
#define NP_WT   0         // bf16 [128][272] -> 34816
#define NP_UT   34816     // bf16 [128][272] -> 69632
#define NP_XS   69632     // bf16 [256][272] -> 139264
#define NP_TS   139264    // bf16 [256][272] -> 208896
#define NP_BENC 208896    // 2 x 128 floats (bp, bc)
#define NP_B1   209920    // 128 floats
#define NP_TOTAL 210432

__global__ __launch_bounds__(512, 1) void node_pre_kernel(
    const float* __restrict__ x_a, const float* __restrict__ x_b,
    const float* __restrict__ Wp, const float* __restrict__ bp,
    const float* __restrict__ Wc, const float* __restrict__ bc,
    const float* __restrict__ W1, const float* __restrict__ b1)
{
    extern __shared__ char smc[];
    uint32_t smb = smem_u32(smc);
    float* benc = (float*)(smc + NP_BENC);
    float* b1sm = (float*)(smc + NP_B1);

    int sidex = blockIdx.y;
    const float* X = sidex ? x_b : x_a;
    __nv_bfloat16* OutA = sidex ? g_A1b : g_A1a;
    __nv_bfloat16* OutC = sidex ? g_C1b : g_C1a;

    int tid = threadIdx.x, lane = tid & 31, w = tid >> 5;
    int nbase = blockIdx.x * 256;

    for (int idx = tid; idx < 256 * 32; idx += 512) {
        int row = idx >> 5, cp = idx & 31;
        int n = nbase + row;
        float4 f = make_float4(0.f, 0.f, 0.f, 0.f);
        if (n < NN) f = *reinterpret_cast<const float4*>(X + (size_t)n * 128 + cp * 4);
        uint2 pk;
        pk.x = bf2u(__floats2bfloat162_rn(f.x, f.y));
        pk.y = bf2u(__floats2bfloat162_rn(f.z, f.w));
        *reinterpret_cast<uint2*>(smc + NP_XS + row * 272 + cp * 8) = pk;
    }
    if (tid < 128) {
        benc[tid]       = bp[tid];
        benc[128 + tid] = bc[tid];
        b1sm[tid]       = b1[tid];
    }

    uint32_t a_lane_off = (uint32_t)(lane & 15) * 272 + (((uint32_t)lane >> 4) << 4);
    uint32_t b_lane_off = (uint32_t)(lane & 7) * 272 + ((((uint32_t)lane >> 3) & 1) << 4);
    int r0 = 16 * w + (lane >> 2), r1 = r0 + 8;
    int cq = (lane & 3) * 2;
    int n0 = nbase + r0, n1 = nbase + r1;

    for (int cc = 0; cc < 2; cc++) {
        const float* W = cc ? Wc : Wp;
        int off = cc ? 128 : 0;
        __nv_bfloat16* Out = cc ? OutC : OutA;

        for (int idx = tid; idx < 128 * 64; idx += 512) {
            int i = idx >> 6, cp = idx & 63;
            float2 fw = *reinterpret_cast<const float2*>(W + i * 128 + cp * 2);
            float2 fu = *reinterpret_cast<const float2*>(W1 + i * 384 + off + cp * 2);
            *(uint32_t*)(smc + NP_WT + i * 272 + cp * 4) = bf2u(__floats2bfloat162_rn(fw.x, fw.y));
            *(uint32_t*)(smc + NP_UT + i * 272 + cp * 4) = bf2u(__floats2bfloat162_rn(fu.x, fu.y));
        }
        __syncthreads();

        float acc[16][4];
        #pragma unroll
        for (int nt = 0; nt < 16; nt++)
            #pragma unroll
            for (int q = 0; q < 4; q++) acc[nt][q] = 0.f;
        mma_rows16(smb + NP_XS + (uint32_t)(16 * w) * 272 + a_lane_off, smb + NP_WT + b_lane_off, acc);

        #pragma unroll
        for (int nt = 0; nt < 16; nt++) {
            int c = nt * 8 + cq;
            float2 bb = *reinterpret_cast<const float2*>(benc + cc * 128 + c);
            float v0 = acc[nt][0] + bb.x, v1 = acc[nt][1] + bb.y;
            float v2 = acc[nt][2] + bb.x, v3 = acc[nt][3] + bb.y;
            v0 = v0 > 0.f ? v0 : 0.01f * v0;
            v1 = v1 > 0.f ? v1 : 0.01f * v1;
            v2 = v2 > 0.f ? v2 : 0.01f * v2;
            v3 = v3 > 0.f ? v3 : 0.01f * v3;
            *(uint32_t*)(smc + NP_TS + r0 * 272 + c * 2) = bf2u(__floats2bfloat162_rn(v0, v1));
            *(uint32_t*)(smc + NP_TS + r1 * 272 + c * 2) = bf2u(__floats2bfloat162_rn(v2, v3));
        }
        __syncwarp();

        #pragma unroll
        for (int nt = 0; nt < 16; nt++)
            #pragma unroll
            for (int q = 0; q < 4; q++) acc[nt][q] = 0.f;
        mma_rows16(smb + NP_TS + (uint32_t)(16 * w) * 272 + a_lane_off, smb + NP_UT + b_lane_off, acc);

        #pragma unroll
        for (int nt = 0; nt < 16; nt++) {
            int c = nt * 8 + cq;
            float bx = (cc == 0) ? b1sm[c] : 0.f;
            float by = (cc == 0) ? b1sm[c + 1] : 0.f;
            uint32_t h0 = bf2u(__floats2bfloat162_rn(acc[nt][0] + bx, acc[nt][1] + by));
            uint32_t h1 = bf2u(__floats2bfloat162_rn(acc[nt][2] + bx, acc[nt][3] + by));
            if (n0 < NN) *(uint32_t*)(Out + (size_t)n0 * 128 + c) = h0;
            if (n1 < NN) *(uint32_t*)(Out + (size_t)n1 * 128 + c) = h1;
        }
        __syncthreads();
    }
}

// ---------------- edge kernel: barrier-free warp-streaming + index prefetch ----------------
#define EP_W2   0          // 128 floats -> 512
#define EP_W1D  512        // bf16 [128][272] -> 35328
#define EP_DIFF 35328      // bf16 [128][272] -> 70144
#define EP_PRES 70144      // bf16 [128][272] -> 104960
#define EP_TOTAL 104960

__global__ __launch_bounds__(256, 2) void edge_mma_kernel(
    const float* __restrict__ x_a, const float* __restrict__ x_b,
    const int* __restrict__ ei,
    const float* __restrict__ W1,
    const float* __restrict__ W2, const float* __restrict__ b2,
    int side)
{
    extern __shared__ char smc[];
    uint32_t smb = smem_u32(smc);
    float* w2s = (float*)(smc + EP_W2);

    const float* src = side ? x_b : x_a;                     // fp32, scatter only
    const __nv_bfloat16* s16 = side ? g_xb16 : g_xa16;
    const __nv_bfloat16* d16 = side ? g_xa16 : g_xb16;
    const __nv_bfloat16* A1 = side ? g_A1b : g_A1a;
    const __nv_bfloat16* C1 = side ? g_C1a : g_C1b;
    float* msg              = side ? g_msg_a : g_msg_b;

    int tid = threadIdx.x, lane = tid & 31, w = tid >> 5;

    for (int idx = tid; idx < 128 * 64; idx += 256) {
        int i = idx >> 6, cp = idx & 63;
        float2 f = *reinterpret_cast<const float2*>(W1 + i * 384 + 256 + cp * 2);
        *(uint32_t*)(smc + EP_W1D + i * 272 + cp * 4) = bf2u(__floats2bfloat162_rn(f.x, f.y));
    }
    if (tid < 128) w2s[tid] = W2[tid];
    float b2s = __ldg(b2);
    __syncthreads();   // only CTA-wide barrier: W1D/w2 ready

    uint32_t a_addr0 = smb + EP_DIFF + (uint32_t)(16 * w + (lane & 15)) * 272 + (((uint32_t)lane >> 4) << 4);
    uint32_t b_base  = smb + EP_W1D  + (uint32_t)(lane & 7) * 272 + ((((uint32_t)lane >> 3) & 1) << 4);
    int r0 = 16 * w + (lane >> 2), r1 = r0 + 8;
    int cq = (lane & 3) * 2;
    int li16 = lane & 15;
    int isdst = lane >> 4;

    const int wstride = gridDim.x * 8;
    int wt = blockIdx.x * 8 + w;
    if (wt >= NWT) return;

    // first tile's batched index load
    int vidx = __ldg(ei + isdst * EE + wt * 16 + li16);

    while (true) {
        // ---- gather (bf16): diff + pres rows for this warp's 16 edges ----
        #pragma unroll
        for (int i = 0; i < 16; i++) {
            int s = __shfl_sync(0xffffffffu, vidx, i);
            int t = __shfl_sync(0xffffffffu, vidx, 16 + i);
            int le = 16 * w + i;
            uint2 pu  = *reinterpret_cast<const uint2*>(s16 + (size_t)s * 128 + 4 * lane);
            uint2 cu  = *reinterpret_cast<const uint2*>(d16 + (size_t)t * 128 + 4 * lane);
            uint2 a1u = *reinterpret_cast<const uint2*>(A1  + (size_t)s * 128 + 4 * lane);
            uint2 c1u = *reinterpret_cast<const uint2*>(C1  + (size_t)t * 128 + 4 * lane);
            uint2 dpk, ppk;
            dpk.x = bf2u(__habs2(__hsub2(u2bf2(pu.x), u2bf2(cu.x))));
            dpk.y = bf2u(__habs2(__hsub2(u2bf2(pu.y), u2bf2(cu.y))));
            ppk.x = bf2u(__hadd2(u2bf2(a1u.x), u2bf2(c1u.x)));
            ppk.y = bf2u(__hadd2(u2bf2(a1u.y), u2bf2(c1u.y)));
            *reinterpret_cast<uint2*>(smc + EP_DIFF + le * 272 + lane * 8) = dpk;
            *reinterpret_cast<uint2*>(smc + EP_PRES + le * 272 + lane * 8) = ppk;
        }
        __syncwarp();

        // ---- prefetch next tile's indices; latency hidden under mma ----
        int wtn = wt + wstride;
        int vnext = 0;
        if (wtn < NWT) vnext = __ldg(ei + isdst * EE + wtn * 16 + li16);

        // ---- mma ----
        float acc[16][4];
        #pragma unroll
        for (int nt = 0; nt < 16; nt++)
            #pragma unroll
            for (int q = 0; q < 4; q++) acc[nt][q] = 0.f;
        mma_rows16(a_addr0, b_base, acc);

        // ---- fused epilogue ----
        float z0 = 0.f, z1 = 0.f;
        #pragma unroll
        for (int nt = 0; nt < 16; nt++) {
            int c = nt * 8 + cq;
            float2 p0 = __bfloat1622float2(*reinterpret_cast<const __nv_bfloat162*>(smc + EP_PRES + r0 * 272 + c * 2));
            float2 p1 = __bfloat1622float2(*reinterpret_cast<const __nv_bfloat162*>(smc + EP_PRES + r1 * 272 + c * 2));
            float2 w2v = *reinterpret_cast<const float2*>(w2s + c);
            z0 += fmaxf(p0.x + acc[nt][0], 0.f) * w2v.x + fmaxf(p0.y + acc[nt][1], 0.f) * w2v.y;
            z1 += fmaxf(p1.x + acc[nt][2], 0.f) * w2v.x + fmaxf(p1.y + acc[nt][3], 0.f) * w2v.y;
        }
        z0 += __shfl_xor_sync(0xffffffffu, z0, 1);
        z0 += __shfl_xor_sync(0xffffffffu, z0, 2);
        z1 += __shfl_xor_sync(0xffffffffu, z1, 1);
        z1 += __shfl_xor_sync(0xffffffffu, z1, 2);
        float sig0 = 1.f / (1.f + __expf(-(z0 + b2s)));
        float sig1 = 1.f / (1.f + __expf(-(z1 + b2s)));
        __syncwarp();   // PRES reads done before next-tile gather overwrites

        // ---- scatter: weights + indices via shfl, fp32 src rows, v4 red ----
        #pragma unroll
        for (int i = 0; i < 16; i++) {
            int s = __shfl_sync(0xffffffffu, vidx, i);
            int t = __shfl_sync(0xffffffffu, vidx, 16 + i);
            float wg = __shfl_sync(0xffffffffu, (i < 8) ? sig0 : sig1, (i & 7) * 4);
            float4 p = *reinterpret_cast<const float4*>(src + (size_t)s * 128 + 4 * lane);
            float* mr = msg + (size_t)t * 128 + 4 * lane;
            red_add_v4(mr, wg * p.x, wg * p.y, wg * p.z, wg * p.w);
        }

        if (wtn >= NWT) break;
        wt = wtn;
        vidx = vnext;
    }
}

// ---------------- final: bf16x3 split-precision mma ----------------
#define FI_BHI 0          // bf16 [128][272] -> 34816
#define FI_BLO 34816      // -> 69632
#define FI_AHI 69632      // bf16 [256][272] -> 139264
#define FI_ALO 139264     // -> 208896
#define FI_BS  208896     // 128 floats
#define FI_TOTAL 209408

__global__ __launch_bounds__(512, 1) void final_kernel(
    const float* __restrict__ x_a, const float* __restrict__ x_b,
    const float* __restrict__ Wrel_ab, const float* __restrict__ brel_ab,
    const float* __restrict__ Wroot_ab, const float* __restrict__ broot_ab,
    const float* __restrict__ Wrel_ba, const float* __restrict__ brel_ba,
    const float* __restrict__ Wroot_ba, const float* __restrict__ broot_ba,
    float* __restrict__ out)
{
    extern __shared__ char smc[];
    uint32_t smb = smem_u32(smc);
    float* bsf = (float*)(smc + FI_BS);

    int side = blockIdx.y;
    const float* x     = side ? x_b : x_a;
    const float* msg   = side ? g_msg_b : g_msg_a;
    const float* Wrel  = side ? Wrel_ab  : Wrel_ba;
    const float* brel  = side ? brel_ab  : brel_ba;
    const float* Wroot = side ? Wroot_ab : Wroot_ba;
    const float* broot = side ? broot_ab : broot_ba;
    float* o = out + (size_t)side * NN * DD;

    int tid = threadIdx.x, lane = tid & 31, w = tid >> 5;
    int nbase = blockIdx.x * 256;

    if (tid < 128) bsf[tid] = brel[tid] + broot[tid];

    uint32_t a_lane_off = (uint32_t)(lane & 15) * 272 + (((uint32_t)lane >> 4) << 4);
    uint32_t b_lane_off = (uint32_t)(lane & 7) * 272 + ((((uint32_t)lane >> 3) & 1) << 4);
    uint32_t a_base = smb + FI_AHI + (uint32_t)(16 * w) * 272 + a_lane_off;
    uint32_t a_base_lo = a_base + (FI_ALO - FI_AHI);

    float acc[16][4];
    #pragma unroll
    for (int nt = 0; nt < 16; nt++)
        #pragma unroll
        for (int q = 0; q < 4; q++) acc[nt][q] = 0.f;

    for (int term = 0; term < 2; term++) {
        const float* Asrc = term ? x : msg;
        const float* Bsrc = term ? Wroot : Wrel;
        if (term) __syncthreads();

        for (int idx = tid; idx < 128 * 64; idx += 512) {
            int i = idx >> 6, cp = idx & 63;
            float2 v = *reinterpret_cast<const float2*>(Bsrc + i * 128 + cp * 2);
            __nv_bfloat162 h = __floats2bfloat162_rn(v.x, v.y);
            float2 hf = __bfloat1622float2(h);
            __nv_bfloat162 l = __floats2bfloat162_rn(v.x - hf.x, v.y - hf.y);
            *(uint32_t*)(smc + FI_BHI + i * 272 + cp * 4) = bf2u(h);
            *(uint32_t*)(smc + FI_BLO + i * 272 + cp * 4) = bf2u(l);
        }
        for (int idx = tid; idx < 256 * 32; idx += 512) {
            int row = idx >> 5, cp = idx & 31;
            int n = nbase + row;
            float4 v = make_float4(0.f, 0.f, 0.f, 0.f);
            if (n < NN) v = *reinterpret_cast<const float4*>(Asrc + (size_t)n * 128 + cp * 4);
            __nv_bfloat162 h0 = __floats2bfloat162_rn(v.x, v.y);
            __nv_bfloat162 h1 = __floats2bfloat162_rn(v.z, v.w);
            float2 f0 = __bfloat1622float2(h0);
            float2 f1 = __bfloat1622float2(h1);
            uint2 ph, pl;
            ph.x = bf2u(h0);
            ph.y = bf2u(h1);
            pl.x = bf2u(__floats2bfloat162_rn(v.x - f0.x, v.y - f0.y));
            pl.y = bf2u(__floats2bfloat162_rn(v.z - f1.x, v.w - f1.y));
            *reinterpret_cast<uint2*>(smc + FI_AHI + row * 272 + cp * 8) = ph;
            *reinterpret_cast<uint2*>(smc + FI_ALO + row * 272 + cp * 8) = pl;
        }
        __syncthreads();

        mma_rows16(a_base,    smb + FI_BHI + b_lane_off, acc);
        mma_rows16(a_base,    smb + FI_BLO + b_lane_off, acc);
        mma_rows16(a_base_lo, smb + FI_BHI + b_lane_off, acc);
    }

    int r0 = 16 * w + (lane >> 2), r1 = r0 + 8;
    int cq = (lane & 3) * 2;
    int n0 = nbase + r0, n1 = nbase + r1;
    #pragma unroll
    for (int nt = 0; nt < 16; nt++) {
        int c = nt * 8 + cq;
        float2 bb = *reinterpret_cast<const float2*>(bsf + c);
        if (n0 < NN) {
            float2 v = make_float2(acc[nt][0] + bb.x, acc[nt][1] + bb.y);
            *reinterpret_cast<float2*>(o + (size_t)n0 * 128 + c) = v;
        }
        if (n1 < NN) {
            float2 v = make_float2(acc[nt][2] + bb.x, acc[nt][3] + bb.y);
            *reinterpret_cast<float2*>(o + (size_t)n1 * 128 + c) = v;
        }
    }
}

// ---------------- host ----------------
extern "C" void kernel_launch(void* const* d_in, const int* in_sizes, int n_in,
                              void* d_out, int out_size)
{
    const float* x_a = (const float*)d_in[0];
    const float* x_b = (const float*)d_in[1];
    const float* Wp  = (const float*)d_in[2];
    const float* bp  = (const float*)d_in[3];
    const float* Wc  = (const float*)d_in[4];
    const float* bc  = (const float*)d_in[5];
    const float* W1  = (const float*)d_in[6];
    const float* b1  = (const float*)d_in[7];
    const float* W2  = (const float*)d_in[8];
    const float* b2  = (const float*)d_in[9];
    const float* Wrel_ab  = (const float*)d_in[10];
    const float* brel_ab  = (const float*)d_in[11];
    const float* Wroot_ab = (const float*)d_in[12];
    const float* broot_ab = (const float*)d_in[13];
    const float* Wrel_ba  = (const float*)d_in[14];
    const float* brel_ba  = (const float*)d_in[15];
    const float* Wroot_ba = (const float*)d_in[16];
    const float* broot_ba = (const float*)d_in[17];
    const int* ei_ab = (const int*)d_in[18];
    const int* ei_ba = (const int*)d_in[19];
    float* out = (float*)d_out;

    cudaFuncSetAttribute(node_pre_kernel, cudaFuncAttributeMaxDynamicSharedMemorySize, NP_TOTAL);
    cudaFuncSetAttribute(edge_mma_kernel, cudaFuncAttributeMaxDynamicSharedMemorySize, EP_TOTAL);
    cudaFuncSetAttribute(final_kernel,    cudaFuncAttributeMaxDynamicSharedMemorySize, FI_TOTAL);

    zero_cvt_kernel<<<(NN * DD / 4 + 255) / 256, 256>>>(x_a, x_b);
    node_pre_kernel<<<dim3((NN + 255) / 256, 2), 512, NP_TOTAL>>>(x_a, x_b, Wp, bp, Wc, bc, W1, b1);
    edge_mma_kernel<<<296, 256, EP_TOTAL>>>(x_a, x_b, ei_ab, W1, W2, b2, 0);
    edge_mma_kernel<<<296, 256, EP_TOTAL>>>(x_a, x_b, ei_ba, W1, W2, b2, 1);
    final_kernel<<<dim3((NN + 255) / 256, 2), 512, FI_TOTAL>>>(
        x_a, x_b, Wrel_ab, brel_ab, Wroot_ab, broot_ab,
        Wrel_ba, brel_ba, Wroot_ba, broot_ba, out);
}

// round 11
// speedup vs baseline: 1.1045x; 1.0089x over previous
#include <cuda_runtime.h>
#include <cuda_bf16.h>
#include <math.h>
#include <stdint.h>

#define NN 50000
#define DD 128
#define EE 500000
#define NWT (EE / 16)    // 31250 pair-tiles, exact

// ---------------- device scratch ----------------
static __device__ __nv_bfloat16 g_A1a[NN*DD];   // lrelu(x_a@Wp.T+bp)@W1p.T + b1
static __device__ __nv_bfloat16 g_C1a[NN*DD];   // lrelu(x_a@Wc.T+bc)@W1c.T
static __device__ __nv_bfloat16 g_A1b[NN*DD];
static __device__ __nv_bfloat16 g_C1b[NN*DD];
static __device__ __nv_bfloat16 g_xa16[NN*DD];  // bf16 copies of x (gather path)
static __device__ __nv_bfloat16 g_xb16[NN*DD];
static __device__ float g_msg_a[NN*DD];
static __device__ float g_msg_b[NN*DD];

__device__ __forceinline__ uint32_t smem_u32(const void* p) {
    uint32_t a;
    asm("{ .reg .u64 t; cvta.to.shared.u64 t, %1; cvt.u32.u64 %0, t; }" : "=r"(a) : "l"(p));
    return a;
}
__device__ __forceinline__ void ldsm_x4(uint32_t* r, uint32_t addr) {
    asm volatile("ldmatrix.sync.aligned.m8n8.x4.shared.b16 {%0,%1,%2,%3}, [%4];"
                 : "=r"(r[0]), "=r"(r[1]), "=r"(r[2]), "=r"(r[3]) : "r"(addr));
}
__device__ __forceinline__ void ldsm_x2(uint32_t* r, uint32_t addr) {
    asm volatile("ldmatrix.sync.aligned.m8n8.x2.shared.b16 {%0,%1}, [%2];"
                 : "=r"(r[0]), "=r"(r[1]) : "r"(addr));
}
__device__ __forceinline__ void mma_bf16(float* c, const uint32_t* a, const uint32_t* b) {
    asm volatile("mma.sync.aligned.m16n8k16.row.col.f32.bf16.bf16.f32 "
                 "{%0,%1,%2,%3}, {%4,%5,%6,%7}, {%8,%9}, {%0,%1,%2,%3};"
                 : "+f"(c[0]), "+f"(c[1]), "+f"(c[2]), "+f"(c[3])
                 : "r"(a[0]), "r"(a[1]), "r"(a[2]), "r"(a[3]), "r"(b[0]), "r"(b[1]));
}
__device__ __forceinline__ void red_add_v4(float* p, float a, float b, float c, float d) {
    asm volatile("red.global.add.v4.f32 [%0], {%1, %2, %3, %4};"
                 :: "l"(p), "f"(a), "f"(b), "f"(c), "f"(d) : "memory");
}
__device__ __forceinline__ __nv_bfloat162 u2bf2(uint32_t u) {
    return *reinterpret_cast<__nv_bfloat162*>(&u);
}
__device__ __forceinline__ uint32_t bf2u(__nv_bfloat162 h) {
    return *reinterpret_cast<uint32_t*>(&h);
}

// 16-row x 128-col x K=128 warp MMA over stride-272 bf16 smem tiles; accumulates.
__device__ __forceinline__ void mma_rows16(uint32_t a_addr0, uint32_t b_base, float acc[16][4]) {
    #pragma unroll
    for (int k = 0; k < 8; k++) {
        uint32_t afrag[4];
        ldsm_x4(afrag, a_addr0 + k * 32);
        uint32_t bb = b_base + k * 32;
        #pragma unroll
        for (int nt = 0; nt < 16; nt++) {
            uint32_t bfrag[2];
            ldsm_x2(bfrag, bb + nt * 2176);
            mma_bf16(acc[nt], afrag, bfrag);
        }
    }
}

// ---------------- zero msg + make bf16 x copies ----------------
__global__ void zero_cvt_kernel(const float* __restrict__ xa, const float* __restrict__ xb) {
    int i = blockIdx.x * blockDim.x + threadIdx.x;
    if (i < NN * DD / 4) {
        float4 z = make_float4(0.f, 0.f, 0.f, 0.f);
        reinterpret_cast<float4*>(g_msg_a)[i] = z;
        reinterpret_cast<float4*>(g_msg_b)[i] = z;
        float4 a = reinterpret_cast<const float4*>(xa)[i];
        float4 b = reinterpret_cast<const float4*>(xb)[i];
        uint2 pa, pb;
        pa.x = bf2u(__floats2bfloat162_rn(a.x, a.y));
        pa.y = bf2u(__floats2bfloat162_rn(a.z, a.w));
        pb.x = bf2u(__floats2bfloat162_rn(b.x, b.y));
        pb.y = bf2u(__floats2bfloat162_rn(b.z, b.w));
        reinterpret_cast<uint2*>(g_xa16)[i] = pa;
        reinterpret_cast<uint2*>(g_xb16)[i] = pb;
    }
}

// ---------------- node precompute: merged chains per side ----------------
#define NP_WT   0         // bf16 [128][272] -> 34816
#define NP_UT   34816     // bf16 [128][272] -> 69632
#define NP_XS   69632     // bf16 [256][272] -> 139264
#define NP_TS   139264    // bf16 [256][272] -> 208896
#define NP_BENC 208896    // 2 x 128 floats (bp, bc)
#define NP_B1   209920    // 128 floats
#define NP_TOTAL 210432

__global__ __launch_bounds__(512, 1) void node_pre_kernel(
    const float* __restrict__ x_a, const float* __restrict__ x_b,
    const float* __restrict__ Wp, const float* __restrict__ bp,
    const float* __restrict__ Wc, const float* __restrict__ bc,
    const float* __restrict__ W1, const float* __restrict__ b1)
{
    extern __shared__ char smc[];
    uint32_t smb = smem_u32(smc);
    float* benc = (float*)(smc + NP_BENC);
    float* b1sm = (float*)(smc + NP_B1);

    int sidex = blockIdx.y;
    const float* X = sidex ? x_b : x_a;
    __nv_bfloat16* OutA = sidex ? g_A1b : g_A1a;
    __nv_bfloat16* OutC = sidex ? g_C1b : g_C1a;

    int tid = threadIdx.x, lane = tid & 31, w = tid >> 5;
    int nbase = blockIdx.x * 256;

    for (int idx = tid; idx < 256 * 32; idx += 512) {
        int row = idx >> 5, cp = idx & 31;
        int n = nbase + row;
        float4 f = make_float4(0.f, 0.f, 0.f, 0.f);
        if (n < NN) f = *reinterpret_cast<const float4*>(X + (size_t)n * 128 + cp * 4);
        uint2 pk;
        pk.x = bf2u(__floats2bfloat162_rn(f.x, f.y));
        pk.y = bf2u(__floats2bfloat162_rn(f.z, f.w));
        *reinterpret_cast<uint2*>(smc + NP_XS + row * 272 + cp * 8) = pk;
    }
    if (tid < 128) {
        benc[tid]       = bp[tid];
        benc[128 + tid] = bc[tid];
        b1sm[tid]       = b1[tid];
    }

    uint32_t a_lane_off = (uint32_t)(lane & 15) * 272 + (((uint32_t)lane >> 4) << 4);
    uint32_t b_lane_off = (uint32_t)(lane & 7) * 272 + ((((uint32_t)lane >> 3) & 1) << 4);
    int r0 = 16 * w + (lane >> 2), r1 = r0 + 8;
    int cq = (lane & 3) * 2;
    int n0 = nbase + r0, n1 = nbase + r1;

    for (int cc = 0; cc < 2; cc++) {
        const float* W = cc ? Wc : Wp;
        int off = cc ? 128 : 0;
        __nv_bfloat16* Out = cc ? OutC : OutA;

        for (int idx = tid; idx < 128 * 64; idx += 512) {
            int i = idx >> 6, cp = idx & 63;
            float2 fw = *reinterpret_cast<const float2*>(W + i * 128 + cp * 2);
            float2 fu = *reinterpret_cast<const float2*>(W1 + i * 384 + off + cp * 2);
            *(uint32_t*)(smc + NP_WT + i * 272 + cp * 4) = bf2u(__floats2bfloat162_rn(fw.x, fw.y));
            *(uint32_t*)(smc + NP_UT + i * 272 + cp * 4) = bf2u(__floats2bfloat162_rn(fu.x, fu.y));
        }
        __syncthreads();

        float acc[16][4];
        #pragma unroll
        for (int nt = 0; nt < 16; nt++)
            #pragma unroll
            for (int q = 0; q < 4; q++) acc[nt][q] = 0.f;
        mma_rows16(smb + NP_XS + (uint32_t)(16 * w) * 272 + a_lane_off, smb + NP_WT + b_lane_off, acc);

        #pragma unroll
        for (int nt = 0; nt < 16; nt++) {
            int c = nt * 8 + cq;
            float2 bb = *reinterpret_cast<const float2*>(benc + cc * 128 + c);
            float v0 = acc[nt][0] + bb.x, v1 = acc[nt][1] + bb.y;
            float v2 = acc[nt][2] + bb.x, v3 = acc[nt][3] + bb.y;
            v0 = v0 > 0.f ? v0 : 0.01f * v0;
            v1 = v1 > 0.f ? v1 : 0.01f * v1;
            v2 = v2 > 0.f ? v2 : 0.01f * v2;
            v3 = v3 > 0.f ? v3 : 0.01f * v3;
            *(uint32_t*)(smc + NP_TS + r0 * 272 + c * 2) = bf2u(__floats2bfloat162_rn(v0, v1));
            *(uint32_t*)(smc + NP_TS + r1 * 272 + c * 2) = bf2u(__floats2bfloat162_rn(v2, v3));
        }
        __syncwarp();

        #pragma unroll
        for (int nt = 0; nt < 16; nt++)
            #pragma unroll
            for (int q = 0; q < 4; q++) acc[nt][q] = 0.f;
        mma_rows16(smb + NP_TS + (uint32_t)(16 * w) * 272 + a_lane_off, smb + NP_UT + b_lane_off, acc);

        #pragma unroll
        for (int nt = 0; nt < 16; nt++) {
            int c = nt * 8 + cq;
            float bx = (cc == 0) ? b1sm[c] : 0.f;
            float by = (cc == 0) ? b1sm[c + 1] : 0.f;
            uint32_t h0 = bf2u(__floats2bfloat162_rn(acc[nt][0] + bx, acc[nt][1] + by));
            uint32_t h1 = bf2u(__floats2bfloat162_rn(acc[nt][2] + bx, acc[nt][3] + by));
            if (n0 < NN) *(uint32_t*)(Out + (size_t)n0 * 128 + c) = h0;
            if (n1 < NN) *(uint32_t*)(Out + (size_t)n1 * 128 + c) = h1;
        }
        __syncthreads();
    }
}

// ---------------- edge kernel: warp-pair tiles, 3 CTAs/SM ----------------
#define EP_W2   0          // 128 floats -> 512
#define EP_W1D  512        // bf16 [128][272] -> 35328
#define EP_DIFF 35328      // 4 pairs x 16x272 -> 52736
#define EP_PRES 52736      // 4 pairs x 16x272 -> 70144
#define EP_ZB   70144      // 4 pairs x 32 floats -> 70656
#define EP_TOTAL 70656

__global__ __launch_bounds__(256, 3) void edge_mma_kernel(
    const float* __restrict__ x_a, const float* __restrict__ x_b,
    const int* __restrict__ ei,
    const float* __restrict__ W1,
    const float* __restrict__ W2, const float* __restrict__ b2,
    int side)
{
    extern __shared__ char smc[];
    uint32_t smb = smem_u32(smc);
    float* w2s  = (float*)(smc + EP_W2);
    float* zbuf = (float*)(smc + EP_ZB);

    const float* src = side ? x_b : x_a;                     // fp32, scatter only
    const __nv_bfloat16* s16 = side ? g_xb16 : g_xa16;
    const __nv_bfloat16* d16 = side ? g_xa16 : g_xb16;
    const __nv_bfloat16* A1 = side ? g_A1b : g_A1a;
    const __nv_bfloat16* C1 = side ? g_C1a : g_C1b;
    float* msg              = side ? g_msg_a : g_msg_b;

    int tid = threadIdx.x, lane = tid & 31, w = tid >> 5;
    int pair = w >> 1, hf = w & 1;

    for (int idx = tid; idx < 128 * 64; idx += 256) {
        int i = idx >> 6, cp = idx & 63;
        float2 f = *reinterpret_cast<const float2*>(W1 + i * 384 + 256 + cp * 2);
        *(uint32_t*)(smc + EP_W1D + i * 272 + cp * 4) = bf2u(__floats2bfloat162_rn(f.x, f.y));
    }
    if (tid < 128) w2s[tid] = W2[tid];
    float b2s = __ldg(b2);
    __syncthreads();

    uint32_t tile_off = (uint32_t)pair * 4352;
    uint32_t a_addr0 = smb + EP_DIFF + tile_off + (uint32_t)(lane & 15) * 272 + (((uint32_t)lane >> 4) << 4);
    uint32_t b_base  = smb + EP_W1D + (uint32_t)(lane & 7) * 272 + ((((uint32_t)lane >> 3) & 1) << 4)
                     + (uint32_t)hf * (8 * 2176);
    int r0 = lane >> 2, r1 = r0 + 8;      // rows within the pair tile
    int cq = (lane & 3) * 2;
    int chf = hf * 64;
    int li16 = lane & 15;
    int isdst = lane >> 4;
    int zidx = pair * 32;

    const int pstride = gridDim.x * 4;
    int pt = blockIdx.x * 4 + pair;
    if (pt >= NWT) return;

    int vidx = __ldg(ei + isdst * EE + pt * 16 + li16);

    while (true) {
        // ---- gather: this warp fills rows 8*hf .. 8*hf+7 of the pair tile ----
        #pragma unroll
        for (int i = 0; i < 8; i++) {
            int ii = 8 * hf + i;
            int s = __shfl_sync(0xffffffffu, vidx, ii);
            int t = __shfl_sync(0xffffffffu, vidx, 16 + ii);
            uint2 pu  = *reinterpret_cast<const uint2*>(s16 + (size_t)s * 128 + 4 * lane);
            uint2 cu  = *reinterpret_cast<const uint2*>(d16 + (size_t)t * 128 + 4 * lane);
            uint2 a1u = *reinterpret_cast<const uint2*>(A1  + (size_t)s * 128 + 4 * lane);
            uint2 c1u = *reinterpret_cast<const uint2*>(C1  + (size_t)t * 128 + 4 * lane);
            uint2 dpk, ppk;
            dpk.x = bf2u(__habs2(__hsub2(u2bf2(pu.x), u2bf2(cu.x))));
            dpk.y = bf2u(__habs2(__hsub2(u2bf2(pu.y), u2bf2(cu.y))));
            ppk.x = bf2u(__hadd2(u2bf2(a1u.x), u2bf2(c1u.x)));
            ppk.y = bf2u(__hadd2(u2bf2(a1u.y), u2bf2(c1u.y)));
            *reinterpret_cast<uint2*>(smc + EP_DIFF + tile_off + ii * 272 + lane * 8) = dpk;
            *reinterpret_cast<uint2*>(smc + EP_PRES + tile_off + ii * 272 + lane * 8) = ppk;
        }
        asm volatile("bar.sync %0, 64;" :: "r"(pair + 1) : "memory");

        // ---- prefetch next pair-tile's indices ----
        int ptn = pt + pstride;
        int vnext = 0;
        if (ptn < NWT) vnext = __ldg(ei + isdst * EE + ptn * 16 + li16);

        // ---- mma: this warp's 8 n-tiles (64 cols) over the shared 16 rows ----
        float acc[8][4];
        #pragma unroll
        for (int nt = 0; nt < 8; nt++)
            #pragma unroll
            for (int q = 0; q < 4; q++) acc[nt][q] = 0.f;
        #pragma unroll
        for (int k = 0; k < 8; k++) {
            uint32_t afrag[4];
            ldsm_x4(afrag, a_addr0 + k * 32);
            uint32_t bb = b_base + k * 32;
            #pragma unroll
            for (int nt = 0; nt < 8; nt++) {
                uint32_t bfrag[2];
                ldsm_x2(bfrag, bb + nt * 2176);
                mma_bf16(acc[nt], afrag, bfrag);
            }
        }

        // ---- epilogue: partial z over this warp's 64 cols ----
        float z0 = 0.f, z1 = 0.f;
        #pragma unroll
        for (int nt = 0; nt < 8; nt++) {
            int c = chf + nt * 8 + cq;
            float2 p0 = __bfloat1622float2(*reinterpret_cast<const __nv_bfloat162*>(smc + EP_PRES + tile_off + r0 * 272 + c * 2));
            float2 p1 = __bfloat1622float2(*reinterpret_cast<const __nv_bfloat162*>(smc + EP_PRES + tile_off + r1 * 272 + c * 2));
            float2 w2v = *reinterpret_cast<const float2*>(w2s + c);
            z0 += fmaxf(p0.x + acc[nt][0], 0.f) * w2v.x + fmaxf(p0.y + acc[nt][1], 0.f) * w2v.y;
            z1 += fmaxf(p1.x + acc[nt][2], 0.f) * w2v.x + fmaxf(p1.y + acc[nt][3], 0.f) * w2v.y;
        }
        z0 += __shfl_xor_sync(0xffffffffu, z0, 1);
        z0 += __shfl_xor_sync(0xffffffffu, z0, 2);
        z1 += __shfl_xor_sync(0xffffffffu, z1, 1);
        z1 += __shfl_xor_sync(0xffffffffu, z1, 2);
        if ((lane & 3) == 0) {
            zbuf[zidx + hf * 16 + r0] = z0;
            zbuf[zidx + hf * 16 + r1] = z1;
        }
        asm volatile("bar.sync %0, 64;" :: "r"(pair + 1) : "memory");

        // ---- combine halves + sigmoid (lanes 0-15 own edge `lane`) ----
        float wg_l = 0.f;
        if (lane < 16) {
            float zz = zbuf[zidx + lane] + zbuf[zidx + 16 + lane] + b2s;
            wg_l = 1.f / (1.f + __expf(-zz));
        }

        // ---- scatter: this warp's 8 edges ----
        #pragma unroll
        for (int i = 0; i < 8; i++) {
            int ii = 8 * hf + i;
            int s = __shfl_sync(0xffffffffu, vidx, ii);
            int t = __shfl_sync(0xffffffffu, vidx, 16 + ii);
            float wg = __shfl_sync(0xffffffffu, wg_l, ii);
            float4 p = *reinterpret_cast<const float4*>(src + (size_t)s * 128 + 4 * lane);
            float* mr = msg + (size_t)t * 128 + 4 * lane;
            red_add_v4(mr, wg * p.x, wg * p.y, wg * p.z, wg * p.w);
        }

        if (ptn >= NWT) break;
        pt = ptn;
        vidx = vnext;
    }
}

// ---------------- final: bf16x3 split-precision mma ----------------
#define FI_BHI 0          // bf16 [128][272] -> 34816
#define FI_BLO 34816      // -> 69632
#define FI_AHI 69632      // bf16 [256][272] -> 139264
#define FI_ALO 139264     // -> 208896
#define FI_BS  208896     // 128 floats
#define FI_TOTAL 209408

__global__ __launch_bounds__(512, 1) void final_kernel(
    const float* __restrict__ x_a, const float* __restrict__ x_b,
    const float* __restrict__ Wrel_ab, const float* __restrict__ brel_ab,
    const float* __restrict__ Wroot_ab, const float* __restrict__ broot_ab,
    const float* __restrict__ Wrel_ba, const float* __restrict__ brel_ba,
    const float* __restrict__ Wroot_ba, const float* __restrict__ broot_ba,
    float* __restrict__ out)
{
    extern __shared__ char smc[];
    uint32_t smb = smem_u32(smc);
    float* bsf = (float*)(smc + FI_BS);

    int side = blockIdx.y;
    const float* x     = side ? x_b : x_a;
    const float* msg   = side ? g_msg_b : g_msg_a;
    const float* Wrel  = side ? Wrel_ab  : Wrel_ba;
    const float* brel  = side ? brel_ab  : brel_ba;
    const float* Wroot = side ? Wroot_ab : Wroot_ba;
    const float* broot = side ? broot_ab : broot_ba;
    float* o = out + (size_t)side * NN * DD;

    int tid = threadIdx.x, lane = tid & 31, w = tid >> 5;
    int nbase = blockIdx.x * 256;

    if (tid < 128) bsf[tid] = brel[tid] + broot[tid];

    uint32_t a_lane_off = (uint32_t)(lane & 15) * 272 + (((uint32_t)lane >> 4) << 4);
    uint32_t b_lane_off = (uint32_t)(lane & 7) * 272 + ((((uint32_t)lane >> 3) & 1) << 4);
    uint32_t a_base = smb + FI_AHI + (uint32_t)(16 * w) * 272 + a_lane_off;
    uint32_t a_base_lo = a_base + (FI_ALO - FI_AHI);

    float acc[16][4];
    #pragma unroll
    for (int nt = 0; nt < 16; nt++)
        #pragma unroll
        for (int q = 0; q < 4; q++) acc[nt][q] = 0.f;

    for (int term = 0; term < 2; term++) {
        const float* Asrc = term ? x : msg;
        const float* Bsrc = term ? Wroot : Wrel;
        if (term) __syncthreads();

        for (int idx = tid; idx < 128 * 64; idx += 512) {
            int i = idx >> 6, cp = idx & 63;
            float2 v = *reinterpret_cast<const float2*>(Bsrc + i * 128 + cp * 2);
            __nv_bfloat162 h = __floats2bfloat162_rn(v.x, v.y);
            float2 hf = __bfloat1622float2(h);
            __nv_bfloat162 l = __floats2bfloat162_rn(v.x - hf.x, v.y - hf.y);
            *(uint32_t*)(smc + FI_BHI + i * 272 + cp * 4) = bf2u(h);
            *(uint32_t*)(smc + FI_BLO + i * 272 + cp * 4) = bf2u(l);
        }
        for (int idx = tid; idx < 256 * 32; idx += 512) {
            int row = idx >> 5, cp = idx & 31;
            int n = nbase + row;
            float4 v = make_float4(0.f, 0.f, 0.f, 0.f);
            if (n < NN) v = *reinterpret_cast<const float4*>(Asrc + (size_t)n * 128 + cp * 4);
            __nv_bfloat162 h0 = __floats2bfloat162_rn(v.x, v.y);
            __nv_bfloat162 h1 = __floats2bfloat162_rn(v.z, v.w);
            float2 f0 = __bfloat1622float2(h0);
            float2 f1 = __bfloat1622float2(h1);
            uint2 ph, pl;
            ph.x = bf2u(h0);
            ph.y = bf2u(h1);
            pl.x = bf2u(__floats2bfloat162_rn(v.x - f0.x, v.y - f0.y));
            pl.y = bf2u(__floats2bfloat162_rn(v.z - f1.x, v.w - f1.y));
            *reinterpret_cast<uint2*>(smc + FI_AHI + row * 272 + cp * 8) = ph;
            *reinterpret_cast<uint2*>(smc + FI_ALO + row * 272 + cp * 8) = pl;
        }
        __syncthreads();

        mma_rows16(a_base,    smb + FI_BHI + b_lane_off, acc);
        mma_rows16(a_base,    smb + FI_BLO + b_lane_off, acc);
        mma_rows16(a_base_lo, smb + FI_BHI + b_lane_off, acc);
    }

    int r0 = 16 * w + (lane >> 2), r1 = r0 + 8;
    int cq = (lane & 3) * 2;
    int n0 = nbase + r0, n1 = nbase + r1;
    #pragma unroll
    for (int nt = 0; nt < 16; nt++) {
        int c = nt * 8 + cq;
        float2 bb = *reinterpret_cast<const float2*>(bsf + c);
        if (n0 < NN) {
            float2 v = make_float2(acc[nt][0] + bb.x, acc[nt][1] + bb.y);
            *reinterpret_cast<float2*>(o + (size_t)n0 * 128 + c) = v;
        }
        if (n1 < NN) {
            float2 v = make_float2(acc[nt][2] + bb.x, acc[nt][3] + bb.y);
            *reinterpret_cast<float2*>(o + (size_t)n1 * 128 + c) = v;
        }
    }
}

// ---------------- host ----------------
extern "C" void kernel_launch(void* const* d_in, const int* in_sizes, int n_in,
                              void* d_out, int out_size)
{
    const float* x_a = (const float*)d_in[0];
    const float* x_b = (const float*)d_in[1];
    const float* Wp  = (const float*)d_in[2];
    const float* bp  = (const float*)d_in[3];
    const float* Wc  = (const float*)d_in[4];
    const float* bc  = (const float*)d_in[5];
    const float* W1  = (const float*)d_in[6];
    const float* b1  = (const float*)d_in[7];
    const float* W2  = (const float*)d_in[8];
    const float* b2  = (const float*)d_in[9];
    const float* Wrel_ab  = (const float*)d_in[10];
    const float* brel_ab  = (const float*)d_in[11];
    const float* Wroot_ab = (const float*)d_in[12];
    const float* broot_ab = (const float*)d_in[13];
    const float* Wrel_ba  = (const float*)d_in[14];
    const float* brel_ba  = (const float*)d_in[15];
    const float* Wroot_ba = (const float*)d_in[16];
    const float* broot_ba = (const float*)d_in[17];
    const int* ei_ab = (const int*)d_in[18];
    const int* ei_ba = (const int*)d_in[19];
    float* out = (float*)d_out;

    cudaFuncSetAttribute(node_pre_kernel, cudaFuncAttributeMaxDynamicSharedMemorySize, NP_TOTAL);
    cudaFuncSetAttribute(edge_mma_kernel, cudaFuncAttributeMaxDynamicSharedMemorySize, EP_TOTAL);
    cudaFuncSetAttribute(final_kernel,    cudaFuncAttributeMaxDynamicSharedMemorySize, FI_TOTAL);

    zero_cvt_kernel<<<(NN * DD / 4 + 255) / 256, 256>>>(x_a, x_b);
    node_pre_kernel<<<dim3((NN + 255) / 256, 2), 512, NP_TOTAL>>>(x_a, x_b, Wp, bp, Wc, bc, W1, b1);
    edge_mma_kernel<<<444, 256, EP_TOTAL>>>(x_a, x_b, ei_ab, W1, W2, b2, 0);
    edge_mma_kernel<<<444, 256, EP_TOTAL>>>(x_a, x_b, ei_ba, W1, W2, b2, 1);
    final_kernel<<<dim3((NN + 255) / 256, 2), 512, FI_TOTAL>>>(
        x_a, x_b, Wrel_ab, brel_ab, Wroot_ab, broot_ab,
        Wrel_ba, brel_ba, Wroot_ba, broot_ba, out);
}